// round 4
// baseline (speedup 1.0000x reference)
#include <cuda_runtime.h>
#include <cstdint>

#define Dn  200
#define Cn  8
#define Gn  10000
#define Vn  20000
#define VGn 50000
#define GLn 500
#define EPSf 1e-8f

// Scratch (no allocations allowed)
__device__ uint8_t g_gen8[Dn * Vn];        // genotypes as u8
__device__ uint8_t g_obs8[Dn * Cn * GLn];  // expression_obs as u8 (values 0..99)
__device__ uint8_t g_gsel[Dn * VGn];       // genotypes[:, sel[vg]] gathered, u8
__device__ float   g_loglib[Dn * Cn];      // log(lib)

// Resolved index-array pointers (classified on device by value range)
__device__ const int* g_p_vg2g;
__device__ const int* g_p_sel;
__device__ const int* g_p_vg2lg;

// ---------------------------------------------------------------------------
// Classify the three VG-sized int arrays by their max value:
//   vg2lg in [0,500), vg2g in [0,10000), sel in [0,20000).
// ---------------------------------------------------------------------------
__global__ void classify_kernel(const int* __restrict__ a,
                                const int* __restrict__ b,
                                const int* __restrict__ c) {
    __shared__ int smax[3][256];
    const int tid = threadIdx.x;
    const int* arrs[3] = {a, b, c};
    for (int j = 0; j < 3; j++) {
        int m = 0;
        for (int i = tid; i < VGn; i += 256) m = max(m, arrs[j][i]);
        smax[j][tid] = m;
    }
    __syncthreads();
    for (int s = 128; s > 0; s >>= 1) {
        if (tid < s)
            for (int j = 0; j < 3; j++)
                smax[j][tid] = max(smax[j][tid], smax[j][tid + s]);
        __syncthreads();
    }
    if (tid == 0) {
        for (int j = 0; j < 3; j++) {
            const int m = smax[j][0];
            if (m < GLn)      g_p_vg2lg = arrs[j];
            else if (m < Gn)  g_p_vg2g  = arrs[j];
            else              g_p_sel   = arrs[j];
        }
    }
}

// ---------------------------------------------------------------------------
// Prep: quantize genotypes & obs to u8, log(lib)
// ---------------------------------------------------------------------------
__global__ void prep_kernel(const float* __restrict__ genotypes,
                            const float* __restrict__ obs,
                            const float* __restrict__ lib) {
    int i = blockIdx.x * blockDim.x + threadIdx.x;
    if (i < Dn * Vn)       g_gen8[i] = (uint8_t)__float2int_rn(genotypes[i]);
    if (i < Dn * Cn * GLn) g_obs8[i] = (uint8_t)__float2int_rn(obs[i]);
    if (i < Dn * Cn)       g_loglib[i] = logf(lib[i]);
}

// ---------------------------------------------------------------------------
// Gather genotypes[d, sel[vg]] -> g_gsel[d, vg]. One block per d; stage the
// 20 KB genotype row in shared so the random gather is LDS, not scattered LDG.
// ---------------------------------------------------------------------------
__global__ void gsel_kernel() {
    __shared__ uint32_t row32[Vn / 4];
    const int* sel = g_p_sel;
    const int d = blockIdx.x;
    const uint32_t* src = (const uint32_t*)(g_gen8 + (size_t)d * Vn);
    for (int j = threadIdx.x; j < Vn / 4; j += blockDim.x) row32[j] = src[j];
    __syncthreads();
    const uint8_t* row = (const uint8_t*)row32;
    uint32_t* dst = (uint32_t*)(g_gsel + (size_t)d * VGn);
    for (int q = threadIdx.x; q < VGn / 4; q += blockDim.x) {
        const int vg = q * 4;
        uint32_t w = (uint32_t)row[sel[vg + 0]]
                   | ((uint32_t)row[sel[vg + 1]] << 8)
                   | ((uint32_t)row[sel[vg + 2]] << 16)
                   | ((uint32_t)row[sel[vg + 3]] << 24);
        dst[q] = w;
    }
}

// ---------------------------------------------------------------------------
// Main kernel. Block = (fixed c, 96 consecutive vg). Thread owns one (c,vg),
// loops over all d. Per-thread shared table F[v] = lgamma(1+v) - cum[v],
// cum[v] = sum_{k<v} log(tc+k), so
//   elbo = (tc+v)*log1p(r) - v*(Q_g + log lib) + F[v]
// (the lgamma(tc) terms cancel exactly).
// ---------------------------------------------------------------------------
#define TPB  96
#define FSTR 101   // stride 101: gcd(101,32)=1 -> good bank spread

__global__ __launch_bounds__(TPB) void main_kernel(
    const float* __restrict__ fc_log,
    const float* __restrict__ lib,
    const float* __restrict__ baseline_log,
    const float* __restrict__ dispersion_log,
    float*       __restrict__ out) {
    __shared__ float F[TPB * FSTR];
    __shared__ float LF[100];

    const int tid = threadIdx.x;
    const int c   = blockIdx.y;
    const int vg  = blockIdx.x * TPB + tid;
    const bool active = (vg < VGn);
    const int vgs = active ? vg : 0;   // safe index for inactive lanes

    // FIX: TPB(96) < 100 — must grid-stride so LF[96..99] get initialized too.
    for (int n = tid; n < 100; n += TPB) LF[n] = lgammaf((float)(n + 1));

    // Per-(c,vg) parameters in registers
    float tc = 1.f, eE = 0.f, R0 = 0.f, R1 = 0.f, R2 = 0.f;
    float Q0 = 0.f, Q1 = 0.f, Q2 = 0.f;
    int lg = 0;
    {
        const int gix = g_p_vg2g[vgs];
        lg = g_p_vg2lg[vgs];
        const float fc = fc_log[c * VGn + vgs];
        const float b  = baseline_log[c * Gn + gix];
        const float dl = dispersion_log[c * Gn + gix];
        const float disp = fminf(expf(dl), 20.0f);
        tc = 1.0f / disp;
        const float itc = 1.0f / (tc + EPSf);
        const float ltc = logf(tc + EPSf);
        eE = EPSf * itc;
        const float e0 = expf(b);
        const float ef = expf(fc);
        R0 = e0 * itc; R1 = R0 * ef; R2 = R1 * ef;
        Q0 = b - ltc;  Q1 = Q0 + fc; Q2 = Q1 + fc;
    }
    __syncthreads();  // LF ready

    // Build per-thread F table: F[v] = LF[v] - sum_{k<v} log(tc+k)
    {
        float cum = 0.f, x = tc;
        float* Ft = F + tid * FSTR;
#pragma unroll 5
        for (int n = 0; n < 100; n++) {
            Ft[n] = LF[n] - cum;
            cum += __logf(x);   // fast log: abs err ~1e-6/term, ~1e-4 worst cum
            x += 1.0f;
        }
    }
    // no sync needed: each thread reads only its own Ft region

    const float* Ft = F + tid * FSTR;
    const uint8_t* gselp = g_gsel + vgs;
    const uint8_t* obsp  = g_obs8 + c * GLn + lg;
    const float*   libp  = lib + c;
    const float*   llibp = g_loglib + c;
    float* outp = out + (size_t)c * VGn + vg;

#pragma unroll 4
    for (int d = 0; d < Dn; d++) {
        const int   gv   = gselp[(size_t)d * VGn];           // u8, coalesced
        const int   v    = obsp[(size_t)d * (Cn * GLn)];     // u8 gather (500B row, L1)
        const float libv = __ldg(libp + d * Cn);             // uniform
        const float llib = __ldg(llibp + d * Cn);            // uniform
        const float vf = (float)v;
        const float R = (gv == 0) ? R0 : ((gv == 1) ? R1 : R2);
        const float Q = (gv == 0) ? Q0 : ((gv == 1) ? Q1 : Q2);
        const float r   = fmaf(R, libv, eE);                 // (mu+EPS)/(tc+EPS)
        const float l1p = log1pf(r);                         // accurate for tiny r (v=0 case)
        const float fv  = Ft[v];                             // LDS
        const float res = fmaf(tc + vf, l1p, fmaf(-vf, Q + llib, fv));
        if (active) outp[(size_t)d * (Cn * VGn)] = res;      // coalesced STG
    }
}

// ---------------------------------------------------------------------------
// Launch: bind inputs by SIZE, not position (robust to metadata ordering).
// ---------------------------------------------------------------------------
extern "C" void kernel_launch(void* const* d_in, const int* in_sizes, int n_in,
                              void* d_out, int out_size) {
    const float* genotypes = nullptr;
    const float* obs       = nullptr;
    const float* fc_log    = nullptr;
    const float* lib       = nullptr;
    const float* cg[2]     = {nullptr, nullptr};   // baseline_log, dispersion_log (in order)
    const int*   vgarr[3]  = {nullptr, nullptr, nullptr};
    int n_cg = 0, n_vg = 0;

    for (int i = 0; i < n_in; i++) {
        switch (in_sizes[i]) {
            case Dn * Vn:        genotypes = (const float*)d_in[i]; break;   // 4,000,000
            case Dn * Cn * GLn:  obs       = (const float*)d_in[i]; break;   //   800,000
            case Cn * VGn:       fc_log    = (const float*)d_in[i]; break;   //   400,000
            case Dn * Cn:        lib       = (const float*)d_in[i]; break;   //     1,600
            case Cn * Gn:        if (n_cg < 2) cg[n_cg++] = (const float*)d_in[i]; break; // 80,000
            case VGn:            if (n_vg < 3) vgarr[n_vg++] = (const int*)d_in[i]; break; // 50,000
            default: break;
        }
    }
    const float* baseline_log   = cg[0];
    const float* dispersion_log = cg[1];
    float* out = (float*)d_out;

    classify_kernel<<<1, 256>>>(vgarr[0], vgarr[1], vgarr[2]);

    const int nprep = Dn * Vn;  // largest prep extent (4M)
    prep_kernel<<<(nprep + 255) / 256, 256>>>(genotypes, obs, lib);
    gsel_kernel<<<Dn, 256>>>();

    dim3 grid((VGn + TPB - 1) / TPB, Cn);
    main_kernel<<<grid, TPB>>>(fc_log, lib, baseline_log, dispersion_log, out);
}

// round 5
// speedup vs baseline: 1.8253x; 1.8253x over previous
#include <cuda_runtime.h>
#include <cstdint>

#define Dn  200
#define Cn  8
#define Gn  10000
#define Vn  20000
#define VGn 50000
#define GLn 500
#define EPSf 1e-8f

// Scratch (no allocations allowed)
__device__ uint8_t g_gen8[Dn * Vn];          // genotypes as u8 [d][v]
__device__ uint8_t g_obsT[Cn * GLn * Dn];    // obs as u8, TRANSPOSED [c][lg][d]
__device__ uint8_t g_gsel[Dn * VGn];         // genotypes[:, sel[vg]] [d][vg]
__device__ float2  g_lib2[Cn * Dn];          // [c][d] = {lib, log(lib)}

// Resolved index-array pointers (classified on device by value range)
__device__ const int* g_p_vg2g;
__device__ const int* g_p_sel;
__device__ const int* g_p_vg2lg;

// ---------------------------------------------------------------------------
// Classify the three VG-sized int arrays by their max value:
//   vg2lg in [0,500), vg2g in [0,10000), sel in [0,20000).
// ---------------------------------------------------------------------------
__global__ void classify_kernel(const int* __restrict__ a,
                                const int* __restrict__ b,
                                const int* __restrict__ c) {
    __shared__ int smax[3][256];
    const int tid = threadIdx.x;
    const int* arrs[3] = {a, b, c};
    for (int j = 0; j < 3; j++) {
        int m = 0;
        for (int i = tid; i < VGn; i += 256) m = max(m, arrs[j][i]);
        smax[j][tid] = m;
    }
    __syncthreads();
    for (int s = 128; s > 0; s >>= 1) {
        if (tid < s)
            for (int j = 0; j < 3; j++)
                smax[j][tid] = max(smax[j][tid], smax[j][tid + s]);
        __syncthreads();
    }
    if (tid == 0) {
        for (int j = 0; j < 3; j++) {
            const int m = smax[j][0];
            if (m < GLn)      g_p_vg2lg = arrs[j];
            else if (m < Gn)  g_p_vg2g  = arrs[j];
            else              g_p_sel   = arrs[j];
        }
    }
}

// ---------------------------------------------------------------------------
// Prep: genotypes->u8; obs->u8 transposed to [c][lg][d]; lib -> {lib, log lib}
// ---------------------------------------------------------------------------
__global__ void prep_kernel(const float* __restrict__ genotypes,
                            const float* __restrict__ obs,
                            const float* __restrict__ lib) {
    int i = blockIdx.x * blockDim.x + threadIdx.x;
    if (i < Dn * Vn) g_gen8[i] = (uint8_t)__float2int_rn(genotypes[i]);
    if (i < Dn * Cn * GLn) {
        const int d  = i / (Cn * GLn);
        const int r  = i - d * (Cn * GLn);
        const int c  = r / GLn;
        const int lg = r - c * GLn;
        g_obsT[(c * GLn + lg) * Dn + d] = (uint8_t)__float2int_rn(obs[i]);
    }
    if (i < Dn * Cn) {
        const int d = i / Cn;
        const int c = i - d * Cn;
        const float lv = lib[i];
        g_lib2[c * Dn + d] = make_float2(lv, logf(lv));
    }
}

// ---------------------------------------------------------------------------
// Gather genotypes[d, sel[vg]] -> g_gsel[d, vg]. One block per d; stage the
// 20 KB genotype row in shared so the random gather is LDS, not scattered LDG.
// ---------------------------------------------------------------------------
__global__ void gsel_kernel() {
    __shared__ uint32_t row32[Vn / 4];
    const int* sel = g_p_sel;
    const int d = blockIdx.x;
    const uint32_t* src = (const uint32_t*)(g_gen8 + (size_t)d * Vn);
    for (int j = threadIdx.x; j < Vn / 4; j += blockDim.x) row32[j] = src[j];
    __syncthreads();
    const uint8_t* row = (const uint8_t*)row32;
    uint32_t* dst = (uint32_t*)(g_gsel + (size_t)d * VGn);
    for (int q = threadIdx.x; q < VGn / 4; q += blockDim.x) {
        const int vg = q * 4;
        uint32_t w = (uint32_t)row[sel[vg + 0]]
                   | ((uint32_t)row[sel[vg + 1]] << 8)
                   | ((uint32_t)row[sel[vg + 2]] << 16)
                   | ((uint32_t)row[sel[vg + 3]] << 24);
        dst[q] = w;
    }
}

// ---------------------------------------------------------------------------
// Main kernel. Block = (fixed c, 128 consecutive vg). Thread owns one (c,vg),
// loops over all d in tiles of 8 (uint2 obs loads).
// HALF-SIZE per-thread table: Fh[j] = lgamma(1+2j) - cum[2j],
//   cum[v] = sum_{k<v} log(tc+k)
// For odd v:  F[v] = Fh[v>>1] + log(v / (tc + v - 1))   (exact identity)
//   elbo = (tc+v)*log1p(r) - v*(Q_g + log lib) + F[v]
// ---------------------------------------------------------------------------
#define TPB 128
#define FH  51   // 51 floats/thread (50 used + pad; odd stride spreads banks)

__global__ __launch_bounds__(TPB) void main_kernel(
    const float* __restrict__ fc_log,
    const float* __restrict__ baseline_log,
    const float* __restrict__ dispersion_log,
    float*       __restrict__ out) {
    __shared__ float  LF[100];
    __shared__ float  Fh[TPB * FH];
    __shared__ float2 slib[Dn];

    const int tid = threadIdx.x;
    const int c   = blockIdx.y;
    const int vg  = blockIdx.x * TPB + tid;
    const bool active = (vg < VGn);
    const int vgs = active ? vg : 0;   // safe index for inactive lanes

    for (int n = tid; n < 100; n += TPB) LF[n] = lgammaf((float)(n + 1));
    for (int n = tid; n < Dn;  n += TPB) slib[n] = g_lib2[c * Dn + n];

    // Per-(c,vg) parameters in registers
    float tc = 1.f, eE = 0.f, R0 = 0.f, R1 = 0.f, R2 = 0.f;
    float Q0 = 0.f, Q1 = 0.f, Q2 = 0.f;
    int lg = 0;
    {
        const int gix = g_p_vg2g[vgs];
        lg = g_p_vg2lg[vgs];
        const float fc = fc_log[c * VGn + vgs];
        const float b  = baseline_log[c * Gn + gix];
        const float dl = dispersion_log[c * Gn + gix];
        const float disp = fminf(expf(dl), 20.0f);
        tc = 1.0f / disp;
        const float itc = 1.0f / (tc + EPSf);
        const float ltc = logf(tc + EPSf);
        eE = EPSf * itc;
        const float e0 = expf(b);
        const float ef = expf(fc);
        R0 = e0 * itc; R1 = R0 * ef; R2 = R1 * ef;
        Q0 = b - ltc;  Q1 = Q0 + fc; Q2 = Q1 + fc;
    }
    __syncthreads();  // LF + slib ready

    // Build per-thread half table
    float* Ft = Fh + tid * FH;
    {
        float cum = 0.f, x = tc;
#pragma unroll 5
        for (int n = 0; n < 100; n += 2) {
            Ft[n >> 1] = LF[n] - cum;
            cum += __logf(x) + __logf(x + 1.0f);
            x += 2.0f;
        }
    }
    // no sync needed: each thread reads only its own Ft region

    const uint8_t* gselp = g_gsel + vgs;
    const uint2*   obsp  = (const uint2*)(g_obsT + (size_t)(c * GLn + lg) * Dn);
    float* outp = out + (size_t)c * VGn + vg;

    for (int t = 0; t < Dn / 8; t++) {
        const uint2 ow = obsp[t];          // 8 obs bytes (this thread's lg row)
        const int dbase = t * 8;
#pragma unroll
        for (int k = 0; k < 8; k++) {
            const int d = dbase + k;
            const uint32_t w = (k < 4) ? ow.x : ow.y;
            const int v = (w >> (8 * (k & 3))) & 0xFF;
            const int gv = gselp[(size_t)d * VGn];            // coalesced u8
            const float2 lv = slib[d];                        // broadcast LDS
            const float vf = (float)v;
            const float R = (gv == 0) ? R0 : ((gv == 1) ? R1 : R2);
            const float Q = (gv == 0) ? Q0 : ((gv == 1) ? Q1 : Q2);
            const float r   = fmaf(R, lv.x, eE);              // (mu+EPS)/(tc+EPS)
            const float l1p = log1pf(r);
            float fv = Ft[v >> 1];                            // LDS half-table
            if (v & 1)
                fv += __logf(__fdividef(vf, tc + vf - 1.0f)); // exact odd fixup
            const float res = fmaf(tc + vf, l1p, fmaf(-vf, Q + lv.y, fv));
            if (active) __stcs(outp + (size_t)d * (Cn * VGn), res);
        }
    }
}

// ---------------------------------------------------------------------------
// Launch: bind inputs by SIZE, not position (robust to metadata ordering).
// ---------------------------------------------------------------------------
extern "C" void kernel_launch(void* const* d_in, const int* in_sizes, int n_in,
                              void* d_out, int out_size) {
    const float* genotypes = nullptr;
    const float* obs       = nullptr;
    const float* fc_log    = nullptr;
    const float* lib       = nullptr;
    const float* cg[2]     = {nullptr, nullptr};   // baseline_log, dispersion_log
    const int*   vgarr[3]  = {nullptr, nullptr, nullptr};
    int n_cg = 0, n_vg = 0;

    for (int i = 0; i < n_in; i++) {
        switch (in_sizes[i]) {
            case Dn * Vn:        genotypes = (const float*)d_in[i]; break;   // 4,000,000
            case Dn * Cn * GLn:  obs       = (const float*)d_in[i]; break;   //   800,000
            case Cn * VGn:       fc_log    = (const float*)d_in[i]; break;   //   400,000
            case Dn * Cn:        lib       = (const float*)d_in[i]; break;   //     1,600
            case Cn * Gn:        if (n_cg < 2) cg[n_cg++] = (const float*)d_in[i]; break; // 80,000
            case VGn:            if (n_vg < 3) vgarr[n_vg++] = (const int*)d_in[i]; break; // 50,000
            default: break;
        }
    }
    const float* baseline_log   = cg[0];
    const float* dispersion_log = cg[1];
    float* out = (float*)d_out;

    classify_kernel<<<1, 256>>>(vgarr[0], vgarr[1], vgarr[2]);

    const int nprep = Dn * Vn;  // largest prep extent (4M)
    prep_kernel<<<(nprep + 255) / 256, 256>>>(genotypes, obs, lib);
    gsel_kernel<<<Dn, 256>>>();

    dim3 grid((VGn + TPB - 1) / TPB, Cn);
    main_kernel<<<grid, TPB>>>(fc_log, baseline_log, dispersion_log, out);
}

// round 6
// speedup vs baseline: 2.6731x; 1.4645x over previous
#include <cuda_runtime.h>
#include <cstdint>

#define Dn  200
#define Cn  8
#define Gn  10000
#define Vn  20000
#define VGn 50000
#define GLn 500
#define EPSf 1e-8f
#define LN2f 0.6931471805599453f

// Scratch (no allocations allowed)
__device__ __align__(16) uint8_t g_gen8[Dn * Vn];       // genotypes u8 [d][v]
__device__ __align__(16) uint8_t g_obsT[Cn * GLn * Dn]; // obs u8 TRANSPOSED [c][lg][d]
__device__ __align__(16) uint8_t g_gsel[Dn * VGn];      // genotypes[:, sel[vg]] [d][vg]
__device__ uint32_t g_gpack[13 * VGn];                  // 2-bit packed gsel: [d/16][vg]
__device__ float    g_libx[Cn * Dn];                    // [c][d] lib
__device__ float    g_liby[Cn * Dn];                    // [c][d] log(lib)

// Resolved index-array pointers (classified on device by value range)
__device__ const int* g_p_vg2g;
__device__ const int* g_p_sel;
__device__ const int* g_p_vg2lg;

// ---------------------------------------------------------------------------
__global__ void classify_kernel(const int* __restrict__ a,
                                const int* __restrict__ b,
                                const int* __restrict__ c) {
    __shared__ int smax[3][256];
    const int tid = threadIdx.x;
    const int* arrs[3] = {a, b, c};
    for (int j = 0; j < 3; j++) {
        int m = 0;
        for (int i = tid; i < VGn; i += 256) m = max(m, arrs[j][i]);
        smax[j][tid] = m;
    }
    __syncthreads();
    for (int s = 128; s > 0; s >>= 1) {
        if (tid < s)
            for (int j = 0; j < 3; j++)
                smax[j][tid] = max(smax[j][tid], smax[j][tid + s]);
        __syncthreads();
    }
    if (tid == 0) {
        for (int j = 0; j < 3; j++) {
            const int m = smax[j][0];
            if (m < GLn)      g_p_vg2lg = arrs[j];
            else if (m < Gn)  g_p_vg2g  = arrs[j];
            else              g_p_sel   = arrs[j];
        }
    }
}

// ---------------------------------------------------------------------------
__global__ void prep_kernel(const float* __restrict__ genotypes,
                            const float* __restrict__ obs,
                            const float* __restrict__ lib) {
    int i = blockIdx.x * blockDim.x + threadIdx.x;
    if (i < Dn * Vn) g_gen8[i] = (uint8_t)__float2int_rn(genotypes[i]);
    if (i < Dn * Cn * GLn) {
        const int d  = i / (Cn * GLn);
        const int r  = i - d * (Cn * GLn);
        const int c  = r / GLn;
        const int lg = r - c * GLn;
        g_obsT[(c * GLn + lg) * Dn + d] = (uint8_t)__float2int_rn(obs[i]);
    }
    if (i < Dn * Cn) {
        const int d = i / Cn;
        const int c = i - d * Cn;
        const float lv = lib[i];
        g_libx[c * Dn + d] = lv;
        g_liby[c * Dn + d] = logf(lv);
    }
}

// ---------------------------------------------------------------------------
// Gather genotypes[d, sel[vg]] -> g_gsel[d, vg] (shared-staged row).
// ---------------------------------------------------------------------------
__global__ void gsel_kernel() {
    __shared__ uint32_t row32[Vn / 4];
    const int* sel = g_p_sel;
    const int d = blockIdx.x;
    const uint32_t* src = (const uint32_t*)(g_gen8 + d * Vn);
    for (int j = threadIdx.x; j < Vn / 4; j += blockDim.x) row32[j] = src[j];
    __syncthreads();
    const uint8_t* row = (const uint8_t*)row32;
    uint32_t* dst = (uint32_t*)(g_gsel + d * VGn);
    for (int q = threadIdx.x; q < VGn / 4; q += blockDim.x) {
        const int vg = q * 4;
        uint32_t w = (uint32_t)row[sel[vg + 0]]
                   | ((uint32_t)row[sel[vg + 1]] << 8)
                   | ((uint32_t)row[sel[vg + 2]] << 16)
                   | ((uint32_t)row[sel[vg + 3]] << 24);
        dst[q] = w;
    }
}

// ---------------------------------------------------------------------------
// Pack g_gsel 2-bit x 16 d's per u32: g_gpack[t][vg], t = d/16.
// ---------------------------------------------------------------------------
__global__ void pack_kernel() {
    const int vg = blockIdx.x * 256 + threadIdx.x;
    if (vg >= VGn) return;
    for (int t = 0; t < 13; t++) {
        uint32_t p = 0;
#pragma unroll
        for (int k = 0; k < 16; k++) {
            const int d = t * 16 + k;
            if (d < Dn) p |= (uint32_t)g_gsel[d * VGn + vg] << (2 * k);
        }
        g_gpack[t * VGn + vg] = p;
    }
}

// ---------------------------------------------------------------------------
// Main kernel. Block = (fixed c, 128 vg). Thread owns (c,vg), loops d in
// tiles of 16: 1 packed-genotype u32 + 2 uint2 obs loads per tile.
// Half-size per-thread table Fh[j] = lgamma(1+2j) - cum[2j];
// odd v: F[v] = Fh[v>>1] + log(v) - log(tc+v-1)   (exact identity).
//   elbo = (tc+v)*ln2*log2(1+r) - v*(Q0 + g*fc + log lib) + F[v]
// ---------------------------------------------------------------------------
#define TPB 128
#define FH  51

__global__ __launch_bounds__(TPB) void main_kernel(
    const float* __restrict__ fc_log,
    const float* __restrict__ baseline_log,
    const float* __restrict__ dispersion_log,
    float*       __restrict__ out) {
    __shared__ float LF[100];
    __shared__ float Fh[TPB * FH];
    __shared__ float slibx[Dn];
    __shared__ float sliby[Dn];

    const int tid = threadIdx.x;
    const int c   = blockIdx.y;
    const int vg  = blockIdx.x * TPB + tid;
    const bool active = (vg < VGn);
    const int vgs = active ? vg : 0;

    for (int n = tid; n < 100; n += TPB) LF[n] = lgammaf((float)(n + 1));
    for (int n = tid; n < Dn;  n += TPB) {
        slibx[n] = g_libx[c * Dn + n];
        sliby[n] = g_liby[c * Dn + n];
    }

    // Per-(c,vg) parameters
    float tc = 1.f, eE = 0.f, R0 = 0.f, R1 = 0.f, R2 = 0.f;
    float Q0 = 0.f, fc = 0.f, tcln2 = 0.f;
    int lg = 0;
    {
        const int gix = g_p_vg2g[vgs];
        lg = g_p_vg2lg[vgs];
        fc = fc_log[c * VGn + vgs];
        const float b  = baseline_log[c * Gn + gix];
        const float dl = dispersion_log[c * Gn + gix];
        const float disp = fminf(expf(dl), 20.0f);
        tc = 1.0f / disp;
        tcln2 = tc * LN2f;
        const float itc = 1.0f / (tc + EPSf);
        const float ltc = logf(tc + EPSf);
        eE = EPSf * itc;
        const float e0 = expf(b);
        const float ef = expf(fc);
        R0 = e0 * itc; R1 = R0 * ef; R2 = R1 * ef;
        Q0 = b - ltc;
    }
    __syncthreads();  // LF + slib ready

    // Build per-thread half table
    float* Ft = Fh + tid * FH;
    {
        float cum = 0.f, x = tc;
#pragma unroll 5
        for (int n = 0; n < 100; n += 2) {
            Ft[n >> 1] = LF[n] - cum;
            cum += __logf(x) + __logf(x + 1.0f);
            x += 2.0f;
        }
    }

    const uint32_t* gpackp = g_gpack + vgs;
    const uint2*    obsp   = (const uint2*)(g_obsT + (c * GLn + lg) * Dn);
    float* outp = out + c * VGn + vg;

#define BODY(k, w, dk)                                                        \
    {                                                                         \
        const int v  = __byte_perm((w), 0, 0x4440 | ((k) & 3));               \
        const int gv = (pack >> (2 * (k))) & 3;                               \
        const float vf = (float)v;                                            \
        const float gf = (float)gv;                                           \
        const float R = (gv == 0) ? R0 : ((gv == 1) ? R1 : R2);               \
        const float r = fmaf(R, slibx[(dk)], eE);                             \
        const float l2 = __log2f(1.0f + r);                                   \
        const float A = fmaf(vf, LN2f, tcln2);                                \
        float fv = Ft[v >> 1];                                                \
        if (v & 1) fv += LN2f * (__log2f(vf) - __log2f(tc + vf - 1.0f));      \
        const float q = fmaf(gf, fc, Q0) + sliby[(dk)];                       \
        float res = fmaf(-vf, q, fv);                                         \
        res = fmaf(A, l2, res);                                               \
        if (active) __stcs(op + (k) * (Cn * VGn), res);                       \
    }

    for (int t = 0; t < 12; t++) {
        const uint32_t pack = gpackp[t * VGn];
        const uint2 a = obsp[2 * t];
        const uint2 b = obsp[2 * t + 1];
        float* op = outp + t * 16 * (Cn * VGn);
        const int db = t * 16;
#pragma unroll
        for (int k = 0; k < 16; k++) {
            const uint32_t w = (k < 8) ? ((k < 4) ? a.x : a.y)
                                       : ((k < 12) ? b.x : b.y);
            BODY(k, w, db + k)
        }
    }
    {   // tail: d = 192..199
        const uint32_t pack = gpackp[12 * VGn];
        const uint2 a = obsp[24];
        float* op = outp + 192 * (Cn * VGn);
#pragma unroll
        for (int k = 0; k < 8; k++) {
            const uint32_t w = (k < 4) ? a.x : a.y;
            BODY(k, w, 192 + k)
        }
    }
#undef BODY
}

// ---------------------------------------------------------------------------
// Launch: bind inputs by SIZE, not position.
// ---------------------------------------------------------------------------
extern "C" void kernel_launch(void* const* d_in, const int* in_sizes, int n_in,
                              void* d_out, int out_size) {
    const float* genotypes = nullptr;
    const float* obs       = nullptr;
    const float* fc_log    = nullptr;
    const float* lib       = nullptr;
    const float* cg[2]     = {nullptr, nullptr};
    const int*   vgarr[3]  = {nullptr, nullptr, nullptr};
    int n_cg = 0, n_vg = 0;

    for (int i = 0; i < n_in; i++) {
        switch (in_sizes[i]) {
            case Dn * Vn:        genotypes = (const float*)d_in[i]; break;
            case Dn * Cn * GLn:  obs       = (const float*)d_in[i]; break;
            case Cn * VGn:       fc_log    = (const float*)d_in[i]; break;
            case Dn * Cn:        lib       = (const float*)d_in[i]; break;
            case Cn * Gn:        if (n_cg < 2) cg[n_cg++] = (const float*)d_in[i]; break;
            case VGn:            if (n_vg < 3) vgarr[n_vg++] = (const int*)d_in[i]; break;
            default: break;
        }
    }
    const float* baseline_log   = cg[0];
    const float* dispersion_log = cg[1];
    float* out = (float*)d_out;

    classify_kernel<<<1, 256>>>(vgarr[0], vgarr[1], vgarr[2]);
    prep_kernel<<<(Dn * Vn + 255) / 256, 256>>>(genotypes, obs, lib);
    gsel_kernel<<<Dn, 256>>>();
    pack_kernel<<<(VGn + 255) / 256, 256>>>();

    dim3 grid((VGn + TPB - 1) / TPB, Cn);
    main_kernel<<<grid, TPB>>>(fc_log, baseline_log, dispersion_log, out);
}